// round 4
// baseline (speedup 1.0000x reference)
#include <cuda_runtime.h>
#include <cuda_bf16.h>

#define NNODES 100000
#define NEDGES 1600000
#define DIM 256
#define DIM2 512
#define BN_EPS 1e-5f

// ---------------- scratch (static device globals; no dynamic alloc) -----------
__device__ int    g_is64;
__device__ int    g_deg[NNODES];
__device__ int    g_rowptr[NNODES + 1];
__device__ int    g_cursor[NNODES];
__device__ int    g_edgesrc[NEDGES];
__device__ float  g_bufA[(size_t)NNODES * DIM];    // h0, later h2
__device__ float  g_bufB[(size_t)NNODES * DIM2];   // h1
__device__ float  g_bnsum[DIM];
__device__ float  g_bnsumsq[DIM];
__device__ float  g_scale[DIM];
__device__ float  g_shift[DIM];

// index dtype detection: int64 arrays have high words == 0 (values < 2^31)
__global__ void k_detect(const int* __restrict__ dst_raw) {
    int is64 = 1;
    for (int i = 0; i < 64; i++)
        if (dst_raw[2 * i + 1] != 0) { is64 = 0; break; }
    g_is64 = is64;
}

__device__ __forceinline__ int load_idx(const void* p, int e, int is64) {
    return is64 ? (int)((const long long*)p)[e] : ((const int*)p)[e];
}

// ---------------- CSR build ---------------------------------------------------
__global__ void k_zero() {
    int i = blockIdx.x * blockDim.x + threadIdx.x;
    if (i < NNODES) g_deg[i] = 0;
    if (i < DIM) { g_bnsum[i] = 0.f; g_bnsumsq[i] = 0.f; }
}

__global__ void k_hist(const void* __restrict__ dst) {
    int e = blockIdx.x * blockDim.x + threadIdx.x;
    int is64 = g_is64;
    if (e < NEDGES) atomicAdd(&g_deg[load_idx(dst, e, is64)], 1);
}

// single-block chunked Hillis-Steele exclusive scan over g_deg -> g_rowptr/g_cursor
__global__ void k_scan() {
    __shared__ int sm[1024];
    __shared__ int s_off;
    int tid = threadIdx.x;
    if (tid == 0) s_off = 0;
    __syncthreads();
    for (int base = 0; base < NNODES; base += 1024) {
        int idx = base + tid;
        int v = (idx < NNODES) ? g_deg[idx] : 0;
        sm[tid] = v;
        __syncthreads();
        for (int s = 1; s < 1024; s <<= 1) {
            int t = (tid >= s) ? sm[tid - s] : 0;
            __syncthreads();
            sm[tid] += t;
            __syncthreads();
        }
        int off = s_off;
        int excl = off + sm[tid] - v;
        if (idx < NNODES) { g_rowptr[idx] = excl; g_cursor[idx] = excl; }
        __syncthreads();
        if (tid == 0) s_off = off + sm[1023];
        __syncthreads();
    }
    if (tid == 0) g_rowptr[NNODES] = s_off;
}

__global__ void k_scatter(const void* __restrict__ src,
                          const void* __restrict__ dst) {
    int e = blockIdx.x * blockDim.x + threadIdx.x;
    int is64 = g_is64;
    if (e < NEDGES) {
        int d = load_idx(dst, e, is64);
        int pos = atomicAdd(&g_cursor[d], 1);
        g_edgesrc[pos] = load_idx(src, e, is64);
    }
}

// ---------------- aggregation: h0 = (1+eps)*x + sum_{src in-edges} x[src] ----
__global__ void k_aggregate(const float* __restrict__ x,
                            const float* __restrict__ eps) {
    int n = blockIdx.x;
    int t = threadIdx.x;   // 256 threads, one column each
    int beg = g_rowptr[n];
    int end = g_rowptr[n + 1];
    float acc = 0.f;
    for (int j = beg; j < end; j++) {
        int s = g_edgesrc[j];
        acc += __ldg(&x[(size_t)s * DIM + t]);
    }
    float e0 = __ldg(&eps[0]);
    g_bufA[(size_t)n * DIM + t] = (1.f + e0) * x[(size_t)n * DIM + t] + acc;
}

// ---------------- SGEMM: C = A[M,K] @ B[K,N] + bias, optional ReLU / BN stats --
// which==0:  A=g_bufA [M,256], B=W1 -> C=g_bufB [M,512], ReLU
// which==1:  A=g_bufB [M,512], B=W2 -> C=g_bufA [M,256], BN stats
#define BM 128
#define BNT 128
#define BK 8
#define TM 8
#define TN 8

__global__ __launch_bounds__(256) void k_gemm(
    int which, const float* __restrict__ B, const float* __restrict__ bias,
    int M, int N, int K)
{
    const float* A = (which == 0) ? g_bufA : g_bufB;
    float* C       = (which == 0) ? g_bufB : g_bufA;
    const int do_relu = (which == 0);
    const int do_bnstats = (which == 1);

    __shared__ float As[BK][BM];
    __shared__ float Bs[BK][BNT];
    __shared__ float s_colsum[BNT];
    __shared__ float s_colsq[BNT];

    int tid = threadIdx.x;
    int tx = tid & 15;          // 16 thread-cols
    int ty = tid >> 4;          // 16 thread-rows
    int row0 = blockIdx.y * BM;
    int col0 = blockIdx.x * BNT;

    // A tile loads: 128 rows x 8 k, float4 along k (2 threads per row)
    int a_row = tid >> 1;
    int a_k = (tid & 1) * 4;
    // B tile loads: 8 rows x 128 n, float4 along n (32 threads per row)
    int b_row = tid >> 5;
    int b_col = (tid & 31) * 4;

    const float* Ag = A + (size_t)(row0 + a_row) * K + a_k;
    bool a_valid = (row0 + a_row) < M;
    const float* Bg = B + (size_t)b_row * N + col0 + b_col;

    float acc[TM][TN];
#pragma unroll
    for (int i = 0; i < TM; i++)
#pragma unroll
        for (int j = 0; j < TN; j++) acc[i][j] = 0.f;

    for (int k0 = 0; k0 < K; k0 += BK) {
        float4 av = a_valid ? *(const float4*)Ag : make_float4(0.f, 0.f, 0.f, 0.f);
        As[a_k + 0][a_row] = av.x;
        As[a_k + 1][a_row] = av.y;
        As[a_k + 2][a_row] = av.z;
        As[a_k + 3][a_row] = av.w;
        *(float4*)&Bs[b_row][b_col] = *(const float4*)Bg;
        __syncthreads();

#pragma unroll
        for (int k = 0; k < BK; k++) {
            float4 a0 = *(const float4*)&As[k][ty * TM];
            float4 a1 = *(const float4*)&As[k][ty * TM + 4];
            float4 b0 = *(const float4*)&Bs[k][tx * TN];
            float4 b1 = *(const float4*)&Bs[k][tx * TN + 4];
            float ar[TM] = {a0.x, a0.y, a0.z, a0.w, a1.x, a1.y, a1.z, a1.w};
            float br[TN] = {b0.x, b0.y, b0.z, b0.w, b1.x, b1.y, b1.z, b1.w};
#pragma unroll
            for (int i = 0; i < TM; i++)
#pragma unroll
                for (int j = 0; j < TN; j++) acc[i][j] = fmaf(ar[i], br[j], acc[i][j]);
        }
        __syncthreads();
        Ag += BK;
        Bg += (size_t)BK * N;
    }

    // epilogue: bias (+relu), store
    float bv[TN];
#pragma unroll
    for (int j = 0; j < TN; j++) bv[j] = __ldg(&bias[col0 + tx * TN + j]);

#pragma unroll
    for (int i = 0; i < TM; i++) {
        int r = row0 + ty * TM + i;
#pragma unroll
        for (int j = 0; j < TN; j++) {
            float v = acc[i][j] + bv[j];
            if (do_relu) v = fmaxf(v, 0.f);
            acc[i][j] = v;
        }
        if (r < M) {
            float4 o0 = make_float4(acc[i][0], acc[i][1], acc[i][2], acc[i][3]);
            float4 o1 = make_float4(acc[i][4], acc[i][5], acc[i][6], acc[i][7]);
            *(float4*)&C[(size_t)r * N + col0 + tx * TN] = o0;
            *(float4*)&C[(size_t)r * N + col0 + tx * TN + 4] = o1;
        }
    }

    // BN statistics (GEMM2 only): per-block column partials -> float global atomics
    if (do_bnstats) {
        if (tid < BNT) { s_colsum[tid] = 0.f; s_colsq[tid] = 0.f; }
        __syncthreads();
#pragma unroll
        for (int j = 0; j < TN; j++) {
            float s = 0.f, s2 = 0.f;
#pragma unroll
            for (int i = 0; i < TM; i++) {
                int r = row0 + ty * TM + i;
                if (r < M) { float v = acc[i][j]; s += v; s2 += v * v; }
            }
            atomicAdd(&s_colsum[tx * TN + j], s);
            atomicAdd(&s_colsq[tx * TN + j], s2);
        }
        __syncthreads();
        if (tid < BNT) {
            atomicAdd(&g_bnsum[col0 + tid], s_colsum[tid]);
            atomicAdd(&g_bnsumsq[col0 + tid], s_colsq[tid]);
        }
    }
}

// ---------------- BN finalize + normalize -------------------------------------
__global__ void k_bnfinal(const float* __restrict__ gamma,
                          const float* __restrict__ beta) {
    int d = threadIdx.x;  // 256
    float mean = g_bnsum[d] * (1.0f / (float)NNODES);
    float var = g_bnsumsq[d] * (1.0f / (float)NNODES) - mean * mean;
    float inv = rsqrtf(var + BN_EPS);
    float sc = inv * gamma[d];
    g_scale[d] = sc;
    g_shift[d] = beta[d] - mean * sc;
}

__global__ void k_norm(float* __restrict__ out) {
    int i = blockIdx.x * blockDim.x + threadIdx.x;   // over N*DIM/4
    if (i >= NNODES * DIM / 4) return;
    int base = i * 4;
    int d = base & (DIM - 1);
    float4 v = *(const float4*)&g_bufA[base];
    float4 o;
    o.x = v.x * g_scale[d + 0] + g_shift[d + 0];
    o.y = v.y * g_scale[d + 1] + g_shift[d + 1];
    o.z = v.z * g_scale[d + 2] + g_shift[d + 2];
    o.w = v.w * g_scale[d + 3] + g_shift[d + 3];
    *(float4*)&out[base] = o;
}

// ---------------- launch ------------------------------------------------------
extern "C" void kernel_launch(void* const* d_in, const int* in_sizes, int n_in,
                              void* d_out, int out_size) {
    const float* node_feats = (const float*)d_in[0];
    const void* src         = d_in[1];
    const void* dst         = d_in[2];
    const float* eps        = (const float*)d_in[3];
    const float* W1         = (const float*)d_in[4];
    const float* b1         = (const float*)d_in[5];
    const float* W2         = (const float*)d_in[6];
    const float* b2         = (const float*)d_in[7];
    const float* gamma      = (const float*)d_in[8];
    const float* beta       = (const float*)d_in[9];
    float* out = (float*)d_out;

    // detect int32 vs int64 indices (JAX default x64-disabled -> int32)
    k_detect<<<1, 1>>>((const int*)dst);

    // CSR build
    k_zero<<<(NNODES + 255) / 256, 256>>>();
    k_hist<<<(NEDGES + 255) / 256, 256>>>(dst);
    k_scan<<<1, 1024>>>();
    k_scatter<<<(NEDGES + 255) / 256, 256>>>(src, dst);

    // aggregation -> h0 (g_bufA)
    k_aggregate<<<NNODES, DIM>>>(node_feats, eps);

    // GEMM1: h1 = relu(h0 @ W1 + b1)   [100000,256]x[256,512] -> g_bufB
    {
        dim3 grid(DIM2 / BNT, (NNODES + BM - 1) / BM);
        k_gemm<<<grid, 256>>>(0, W1, b1, NNODES, DIM2, DIM);
    }
    // GEMM2: h2 = h1 @ W2 + b2         [100000,512]x[512,256] -> g_bufA, BN stats
    {
        dim3 grid(DIM / BNT, (NNODES + BM - 1) / BM);
        k_gemm<<<grid, 256>>>(1, W2, b2, NNODES, DIM, DIM2);
    }

    // BN finalize + normalize
    k_bnfinal<<<1, DIM>>>(gamma, beta);
    k_norm<<<(NNODES * DIM / 4 + 255) / 256, 256>>>(out);
}

// round 6
// speedup vs baseline: 1.6138x; 1.6138x over previous
#include <cuda_runtime.h>
#include <cuda_bf16.h>
#include <cstdint>

#define NNODES 100000
#define NEDGES 1600000
#define DIM 256
#define DIM2 512
#define BN_EPS 1e-5f

// ---------------- scratch (static device globals; no dynamic alloc) -----------
__device__ int    g_is64;
__device__ int    g_deg[NNODES];
__device__ int    g_rowptr[NNODES + 1];
__device__ int    g_cursor[NNODES];
__device__ int    g_edgesrc[NEDGES];
__device__ float  g_bufA[(size_t)NNODES * DIM];    // h0, later h2
__device__ float  g_bufB[(size_t)NNODES * DIM2];   // h1
__device__ float  g_WT1[(size_t)DIM2 * DIM];       // W1^T  [512][256]
__device__ float  g_WT2[(size_t)DIM * DIM2];       // W2^T  [256][512]
__device__ float  g_bnsum[DIM];
__device__ float  g_bnsumsq[DIM];
__device__ float  g_scale[DIM];
__device__ float  g_shift[DIM];

#define SCAN_CHUNK 1024
#define SCAN_NB ((NNODES + SCAN_CHUNK - 1) / SCAN_CHUNK)   // 98
__device__ int g_bsum[SCAN_NB];
__device__ int g_boff[SCAN_NB];

// ---------------- index dtype detection ---------------------------------------
__global__ void k_detect(const int* __restrict__ dst_raw) {
    int is64 = 1;
    for (int i = 0; i < 64; i++)
        if (dst_raw[2 * i + 1] != 0) { is64 = 0; break; }
    g_is64 = is64;
}
__device__ __forceinline__ int load_idx(const void* p, int e, int is64) {
    return is64 ? (int)((const long long*)p)[e] : ((const int*)p)[e];
}

// ---------------- CSR build ---------------------------------------------------
__global__ void k_zero() {
    int i = blockIdx.x * blockDim.x + threadIdx.x;
    if (i < NNODES) g_deg[i] = 0;
    if (i < DIM) { g_bnsum[i] = 0.f; g_bnsumsq[i] = 0.f; }
}
__global__ void k_hist(const void* __restrict__ dst) {
    int e = blockIdx.x * blockDim.x + threadIdx.x;
    int is64 = g_is64;
    if (e < NEDGES) atomicAdd(&g_deg[load_idx(dst, e, is64)], 1);
}
__global__ void k_scan1() {
    __shared__ int sm[SCAN_CHUNK];
    int b = blockIdx.x, tid = threadIdx.x;
    int idx = b * SCAN_CHUNK + tid;
    int v = (idx < NNODES) ? g_deg[idx] : 0;
    sm[tid] = v;
    __syncthreads();
    for (int s = 1; s < SCAN_CHUNK; s <<= 1) {
        int t = (tid >= s) ? sm[tid - s] : 0;
        __syncthreads();
        sm[tid] += t;
        __syncthreads();
    }
    if (idx < NNODES) g_rowptr[idx] = sm[tid] - v;   // exclusive, block-local
    if (tid == SCAN_CHUNK - 1) g_bsum[b] = sm[tid];
}
__global__ void k_scan2() {
    __shared__ int sm[128];
    int tid = threadIdx.x;
    int v = (tid < SCAN_NB) ? g_bsum[tid] : 0;
    sm[tid] = v;
    __syncthreads();
    for (int s = 1; s < 128; s <<= 1) {
        int t = (tid >= s) ? sm[tid - s] : 0;
        __syncthreads();
        sm[tid] += t;
        __syncthreads();
    }
    if (tid < SCAN_NB) g_boff[tid] = sm[tid] - v;    // exclusive
    if (tid == 127) g_rowptr[NNODES] = sm[127];
}
__global__ void k_scan3() {
    int i = blockIdx.x * blockDim.x + threadIdx.x;
    if (i < NNODES) {
        int r = g_rowptr[i] + g_boff[i >> 10];
        g_rowptr[i] = r;
        g_cursor[i] = r;
    }
}
__global__ void k_scatter(const void* __restrict__ src,
                          const void* __restrict__ dst) {
    int e = blockIdx.x * blockDim.x + threadIdx.x;
    int is64 = g_is64;
    if (e < NEDGES) {
        int d = load_idx(dst, e, is64);
        int pos = atomicAdd(&g_cursor[d], 1);
        g_edgesrc[pos] = load_idx(src, e, is64);
    }
}

// ---------------- aggregation: h0 = (1+eps)*x + sum_{in-edges} x[src] ---------
__global__ void k_aggregate(const float* __restrict__ x,
                            const float* __restrict__ eps) {
    int n = blockIdx.x;
    int t = threadIdx.x;   // 256 threads, one column each
    int beg = g_rowptr[n];
    int end = g_rowptr[n + 1];
    float acc = 0.f;
    for (int j = beg; j < end; j++) {
        int s = g_edgesrc[j];
        acc += __ldg(&x[(size_t)s * DIM + t]);
    }
    float e0 = __ldg(&eps[0]);
    g_bufA[(size_t)n * DIM + t] = (1.f + e0) * x[(size_t)n * DIM + t] + acc;
}

// ---------------- weight transpose: WT[n][k] = W[k][n] ------------------------
__global__ void k_transpose(const float* __restrict__ W, int rows, int cols, int which) {
    __shared__ float t[32][33];
    float* out = which ? g_WT2 : g_WT1;
    int bx = blockIdx.x * 32, by = blockIdx.y * 32;
    for (int i = threadIdx.y; i < 32; i += 8)
        t[i][threadIdx.x] = W[(size_t)(by + i) * cols + bx + threadIdx.x];
    __syncthreads();
    for (int i = threadIdx.y; i < 32; i += 8)
        out[(size_t)(bx + i) * rows + by + threadIdx.x] = t[threadIdx.x][i];
}

// ---------------- tf32 mma.sync GEMM: C = A[M,K] @ WT[N,K]^T + bias -----------
// which==0: A=g_bufA, B=g_WT1, C=g_bufB, N=512, K=256, ReLU
// which==1: A=g_bufB, B=g_WT2, C=g_bufA, N=256, K=512
#define GBM 128
#define GBN 128
#define GBK 32
#define SPAD 36     // smem row stride in floats (bank-conflict-free fragments)

__device__ __forceinline__ uint32_t f2tf32(float f) {
    uint32_t r;
    asm("cvt.rna.tf32.f32 %0, %1;" : "=r"(r) : "f"(f));
    return r;
}

__global__ __launch_bounds__(256)
void k_gemm_tc(int which, const float* __restrict__ bias, int M, int N, int K) {
    const float* A = which ? g_bufB : g_bufA;
    const float* B = which ? g_WT2 : g_WT1;
    float* C       = which ? g_bufA : g_bufB;
    const int do_relu = (which == 0);

    __shared__ uint32_t sA[GBM * SPAD];   // tf32 bits
    __shared__ uint32_t sB[GBN * SPAD];

    int tid = threadIdx.x;
    int wid = tid >> 5;
    int lane = tid & 31;
    int warp_m = wid & 1;       // 2 warps along M (64 rows each)
    int warp_n = wid >> 1;      // 4 warps along N (32 cols each)
    int row0 = blockIdx.y * GBM;
    int col0 = blockIdx.x * GBN;

    int gid = lane >> 2;        // 0..7
    int tig = lane & 3;         // 0..3

    float acc[4][4][4];
#pragma unroll
    for (int i = 0; i < 4; i++)
#pragma unroll
        for (int j = 0; j < 4; j++)
#pragma unroll
            for (int c = 0; c < 4; c++) acc[i][j][c] = 0.f;

    for (int kt = 0; kt < K; kt += GBK) {
        // load tiles: 128 rows x 32 floats each; 256 threads x 4 float4 per array
#pragma unroll
        for (int i = 0; i < 4; i++) {
            int lin = i * 256 + tid;          // 0..1023 float4 slots
            int row = lin >> 3;               // 0..127
            int f = lin & 7;                  // 0..7
            int so = row * SPAD + f * 4;
            int gr = row0 + row;
            float4 av = (gr < M) ? *(const float4*)&A[(size_t)gr * K + kt + f * 4]
                                 : make_float4(0.f, 0.f, 0.f, 0.f);
            sA[so + 0] = f2tf32(av.x); sA[so + 1] = f2tf32(av.y);
            sA[so + 2] = f2tf32(av.z); sA[so + 3] = f2tf32(av.w);
            float4 bv = *(const float4*)&B[(size_t)(col0 + row) * K + kt + f * 4];
            sB[so + 0] = f2tf32(bv.x); sB[so + 1] = f2tf32(bv.y);
            sB[so + 2] = f2tf32(bv.z); sB[so + 3] = f2tf32(bv.w);
        }
        __syncthreads();

#pragma unroll
        for (int kk = 0; kk < GBK; kk += 8) {
            uint32_t af[4][4], bf[4][2];
#pragma unroll
            for (int mt = 0; mt < 4; mt++) {
                int r = warp_m * 64 + mt * 16 + gid;
                af[mt][0] = sA[r * SPAD + kk + tig];
                af[mt][1] = sA[(r + 8) * SPAD + kk + tig];
                af[mt][2] = sA[r * SPAD + kk + tig + 4];
                af[mt][3] = sA[(r + 8) * SPAD + kk + tig + 4];
            }
#pragma unroll
            for (int nt = 0; nt < 4; nt++) {
                int n = warp_n * 32 + nt * 8 + gid;
                bf[nt][0] = sB[n * SPAD + kk + tig];
                bf[nt][1] = sB[n * SPAD + kk + tig + 4];
            }
#pragma unroll
            for (int mt = 0; mt < 4; mt++)
#pragma unroll
                for (int nt = 0; nt < 4; nt++) {
                    asm volatile(
                        "mma.sync.aligned.m16n8k8.row.col.f32.tf32.tf32.f32 "
                        "{%0,%1,%2,%3}, {%4,%5,%6,%7}, {%8,%9}, {%0,%1,%2,%3};"
                        : "+f"(acc[mt][nt][0]), "+f"(acc[mt][nt][1]),
                          "+f"(acc[mt][nt][2]), "+f"(acc[mt][nt][3])
                        : "r"(af[mt][0]), "r"(af[mt][1]), "r"(af[mt][2]), "r"(af[mt][3]),
                          "r"(bf[nt][0]), "r"(bf[nt][1]));
                }
        }
        __syncthreads();
    }

    // epilogue: bias (+relu), store float2 pairs
#pragma unroll
    for (int nt = 0; nt < 4; nt++) {
        int cb = col0 + warp_n * 32 + nt * 8 + 2 * tig;
        float bv0 = __ldg(&bias[cb]);
        float bv1 = __ldg(&bias[cb + 1]);
#pragma unroll
        for (int mt = 0; mt < 4; mt++) {
            int r = row0 + warp_m * 64 + mt * 16 + gid;
            float v0 = acc[mt][nt][0] + bv0;
            float v1 = acc[mt][nt][1] + bv1;
            float v2 = acc[mt][nt][2] + bv0;
            float v3 = acc[mt][nt][3] + bv1;
            if (do_relu) {
                v0 = fmaxf(v0, 0.f); v1 = fmaxf(v1, 0.f);
                v2 = fmaxf(v2, 0.f); v3 = fmaxf(v3, 0.f);
            }
            if (r < M)     *(float2*)&C[(size_t)r * N + cb]       = make_float2(v0, v1);
            if (r + 8 < M) *(float2*)&C[(size_t)(r + 8) * N + cb] = make_float2(v2, v3);
        }
    }
}

// ---------------- BN stats / finalize / normalize -----------------------------
__global__ void k_bnstats() {
    int col = threadIdx.x;        // 256
    int row0 = blockIdx.x * 128;
    float s = 0.f, s2 = 0.f;
    for (int r = 0; r < 128; r++) {
        int row = row0 + r;
        if (row < NNODES) {
            float v = g_bufA[(size_t)row * DIM + col];
            s += v;
            s2 += v * v;
        }
    }
    atomicAdd(&g_bnsum[col], s);
    atomicAdd(&g_bnsumsq[col], s2);
}
__global__ void k_bnfinal(const float* __restrict__ gamma,
                          const float* __restrict__ beta) {
    int d = threadIdx.x;  // 256
    float mean = g_bnsum[d] * (1.0f / (float)NNODES);
    float var = g_bnsumsq[d] * (1.0f / (float)NNODES) - mean * mean;
    float inv = rsqrtf(var + BN_EPS);
    float sc = inv * gamma[d];
    g_scale[d] = sc;
    g_shift[d] = beta[d] - mean * sc;
}
__global__ void k_norm(float* __restrict__ out) {
    int i = blockIdx.x * blockDim.x + threadIdx.x;   // over N*DIM/4
    if (i >= NNODES * DIM / 4) return;
    int base = i * 4;
    int d = base & (DIM - 1);
    float4 v = *(const float4*)&g_bufA[base];
    float4 o;
    o.x = v.x * g_scale[d + 0] + g_shift[d + 0];
    o.y = v.y * g_scale[d + 1] + g_shift[d + 1];
    o.z = v.z * g_scale[d + 2] + g_shift[d + 2];
    o.w = v.w * g_scale[d + 3] + g_shift[d + 3];
    *(float4*)&out[base] = o;
}

// ---------------- launch ------------------------------------------------------
extern "C" void kernel_launch(void* const* d_in, const int* in_sizes, int n_in,
                              void* d_out, int out_size) {
    const float* node_feats = (const float*)d_in[0];
    const void* src         = d_in[1];
    const void* dst         = d_in[2];
    const float* eps        = (const float*)d_in[3];
    const float* W1         = (const float*)d_in[4];
    const float* b1         = (const float*)d_in[5];
    const float* W2         = (const float*)d_in[6];
    const float* b2         = (const float*)d_in[7];
    const float* gamma      = (const float*)d_in[8];
    const float* beta       = (const float*)d_in[9];
    float* out = (float*)d_out;

    k_detect<<<1, 1>>>((const int*)dst);

    // CSR build
    k_zero<<<(NNODES + 255) / 256, 256>>>();
    k_hist<<<(NEDGES + 255) / 256, 256>>>(dst);
    k_scan1<<<SCAN_NB, SCAN_CHUNK>>>();
    k_scan2<<<1, 128>>>();
    k_scan3<<<(NNODES + 255) / 256, 256>>>();
    k_scatter<<<(NEDGES + 255) / 256, 256>>>(src, dst);

    // weight transposes (independent of the above)
    {
        dim3 b(32, 8);
        k_transpose<<<dim3(DIM2 / 32, DIM / 32), b>>>(W1, DIM, DIM2, 0);
        k_transpose<<<dim3(DIM / 32, DIM2 / 32), b>>>(W2, DIM2, DIM, 1);
    }

    // aggregation -> h0 (g_bufA)
    k_aggregate<<<NNODES, DIM>>>(node_feats, eps);

    const int MROWS = (NNODES + GBM - 1) / GBM;   // 782
    // GEMM1: h1 = relu(h0 @ W1 + b1) -> g_bufB
    k_gemm_tc<<<dim3(DIM2 / GBN, MROWS), 256>>>(0, b1, NNODES, DIM2, DIM);
    // GEMM2: h2 = h1 @ W2 + b2 -> g_bufA
    k_gemm_tc<<<dim3(DIM / GBN, MROWS), 256>>>(1, b2, NNODES, DIM, DIM2);

    // BN stats + finalize + normalize
    k_bnstats<<<(NNODES + 127) / 128, 256>>>();
    k_bnfinal<<<1, DIM>>>(gamma, beta);
    k_norm<<<(NNODES * DIM / 4 + 255) / 256, 256>>>(out);
}

// round 7
// speedup vs baseline: 2.2896x; 1.4188x over previous
#include <cuda_runtime.h>
#include <cuda_bf16.h>
#include <cstdint>

#define NNODES 100000
#define NEDGES 1600000
#define DIM 256
#define DIM2 512
#define BN_EPS 1e-5f

// ---------------- scratch (static device globals; no dynamic alloc) -----------
__device__ int    g_is64;
__device__ int    g_deg[NNODES];
__device__ int    g_rowptr[NNODES + 1];
__device__ int    g_cursor[NNODES];
__device__ int    g_edgesrc[NEDGES];
__device__ float  g_bufA[(size_t)NNODES * DIM];    // h0, later h2
__device__ float  g_bufB[(size_t)NNODES * DIM2];   // h1
__device__ float  g_WT1[(size_t)DIM2 * DIM];       // W1^T  [512][256]
__device__ float  g_WT2[(size_t)DIM * DIM2];       // W2^T  [256][512]
__device__ float  g_bnsum[DIM];
__device__ float  g_bnsumsq[DIM];
__device__ float  g_scale[DIM];
__device__ float  g_shift[DIM];

#define SCAN_CHUNK 1024
#define SCAN_NB ((NNODES + SCAN_CHUNK - 1) / SCAN_CHUNK)   // 98
__device__ int g_bsum[SCAN_NB];
__device__ int g_boff[SCAN_NB];

// ---------------- helpers ------------------------------------------------------
__device__ __forceinline__ uint32_t smem_u32(const void* p) {
    uint32_t a;
    asm("{ .reg .u64 t; cvta.to.shared.u64 t, %1; cvt.u32.u64 %0, t; }"
        : "=r"(a) : "l"(p));
    return a;
}
__device__ __forceinline__ uint32_t f2tf32(float f) {
    uint32_t r;
    asm("cvt.rna.tf32.f32 %0, %1;" : "=r"(r) : "f"(f));
    return r;
}
#define CP_ASYNC16Z(dst, src, sz) \
    asm volatile("cp.async.cg.shared.global [%0], [%1], 16, %2;" \
                 :: "r"(dst), "l"(src), "r"(sz) : "memory")
#define CP_ASYNC16(dst, src) \
    asm volatile("cp.async.cg.shared.global [%0], [%1], 16;" \
                 :: "r"(dst), "l"(src) : "memory")
#define CP_COMMIT() asm volatile("cp.async.commit_group;" ::: "memory")
#define CP_WAIT(n)  asm volatile("cp.async.wait_group %0;" :: "n"(n) : "memory")

__device__ __forceinline__ int load_idx(const void* p, int e, int is64) {
    return is64 ? (int)((const long long*)p)[e] : ((const int*)p)[e];
}

// ---------------- zero + index-dtype detect ------------------------------------
__global__ void k_zero(const int* __restrict__ dst_raw) {
    int i = blockIdx.x * blockDim.x + threadIdx.x;
    if (i < NNODES) g_deg[i] = 0;
    if (i < DIM) { g_bnsum[i] = 0.f; g_bnsumsq[i] = 0.f; }
    if (i == 0) {
        int is64 = 1;
        for (int k = 0; k < 64; k++)
            if (dst_raw[2 * k + 1] != 0) { is64 = 0; break; }
        g_is64 = is64;
    }
}

// ---------------- CSR build ----------------------------------------------------
__global__ void k_hist(const void* __restrict__ dst) {
    int e = blockIdx.x * blockDim.x + threadIdx.x;
    int is64 = g_is64;
    if (e < NEDGES) atomicAdd(&g_deg[load_idx(dst, e, is64)], 1);
}
__global__ void k_scan1() {
    __shared__ int sm[SCAN_CHUNK];
    int b = blockIdx.x, tid = threadIdx.x;
    int idx = b * SCAN_CHUNK + tid;
    int v = (idx < NNODES) ? g_deg[idx] : 0;
    sm[tid] = v;
    __syncthreads();
    for (int s = 1; s < SCAN_CHUNK; s <<= 1) {
        int t = (tid >= s) ? sm[tid - s] : 0;
        __syncthreads();
        sm[tid] += t;
        __syncthreads();
    }
    if (idx < NNODES) g_rowptr[idx] = sm[tid] - v;
    if (tid == SCAN_CHUNK - 1) g_bsum[b] = sm[tid];
}
__global__ void k_scan2() {
    __shared__ int sm[128];
    int tid = threadIdx.x;
    int v = (tid < SCAN_NB) ? g_bsum[tid] : 0;
    sm[tid] = v;
    __syncthreads();
    for (int s = 1; s < 128; s <<= 1) {
        int t = (tid >= s) ? sm[tid - s] : 0;
        __syncthreads();
        sm[tid] += t;
        __syncthreads();
    }
    if (tid < SCAN_NB) g_boff[tid] = sm[tid] - v;
    if (tid == 127) g_rowptr[NNODES] = sm[127];
}
__global__ void k_scan3() {
    int i = blockIdx.x * blockDim.x + threadIdx.x;
    if (i < NNODES) {
        int r = g_rowptr[i] + g_boff[i >> 10];
        g_rowptr[i] = r;
        g_cursor[i] = r;
    }
}
__global__ void k_scatter(const void* __restrict__ src,
                          const void* __restrict__ dst) {
    int e = blockIdx.x * blockDim.x + threadIdx.x;
    int is64 = g_is64;
    if (e < NEDGES) {
        int d = load_idx(dst, e, is64);
        int pos = atomicAdd(&g_cursor[d], 1);
        g_edgesrc[pos] = load_idx(src, e, is64);
    }
}

// ---------------- aggregation: h0 = (1+eps)*x + sum_{in-edges} x[src] ----------
__global__ void k_aggregate(const float* __restrict__ x,
                            const float* __restrict__ eps) {
    int n = blockIdx.x;
    int t = threadIdx.x;   // 256 threads, one column each
    int beg = g_rowptr[n];
    int end = g_rowptr[n + 1];
    float acc0 = 0.f, acc1 = 0.f;
    int j = beg;
    for (; j + 2 <= end; j += 2) {
        int s0 = g_edgesrc[j];
        int s1 = g_edgesrc[j + 1];
        acc0 += __ldg(&x[(size_t)s0 * DIM + t]);
        acc1 += __ldg(&x[(size_t)s1 * DIM + t]);
    }
    if (j < end) acc0 += __ldg(&x[(size_t)g_edgesrc[j] * DIM + t]);
    float e0 = __ldg(&eps[0]);
    g_bufA[(size_t)n * DIM + t] =
        (1.f + e0) * x[(size_t)n * DIM + t] + (acc0 + acc1);
}

// ---------------- weight transpose: WT[n][k] = W[k][n] -------------------------
__global__ void k_transpose(const float* __restrict__ W, int rows, int cols, int which) {
    __shared__ float t[32][33];
    float* out = which ? g_WT2 : g_WT1;
    int bx = blockIdx.x * 32, by = blockIdx.y * 32;
    for (int i = threadIdx.y; i < 32; i += 8)
        t[i][threadIdx.x] = W[(size_t)(by + i) * cols + bx + threadIdx.x];
    __syncthreads();
    for (int i = threadIdx.y; i < 32; i += 8)
        out[(size_t)(bx + i) * rows + by + threadIdx.x] = t[threadIdx.x][i];
}

// ---------------- tf32 mma.sync GEMM, cp.async 2-stage pipeline ----------------
// which==0: A=g_bufA [M,256], B=g_WT1 -> C=g_bufB [M,512], ReLU
// which==1: A=g_bufB [M,512], B=g_WT2 -> C=g_bufA [M,256], fused BN stats
#define GBM 128
#define GBN 128
#define GBK 16
#define SPAD 20     // floats per smem row (16 data + 4 pad); 80B, 16B-aligned

__global__ __launch_bounds__(256, 2)
void k_gemm_tc(int which, const float* __restrict__ bias, int M, int N, int K) {
    const float* A  = which ? g_bufB : g_bufA;
    const float* Bw = which ? g_WT2 : g_WT1;
    float* C        = which ? g_bufA : g_bufB;
    const int do_relu = (which == 0);

    __shared__ float sA[2][GBM * SPAD];   // 2 stages x 10KB
    __shared__ float sB[2][GBM * SPAD];
    __shared__ float s_bns[GBN], s_bnq[GBN];

    int tid = threadIdx.x;
    int wid = tid >> 5;
    int lane = tid & 31;
    int warp_m = wid & 1;        // 2 warps along M (64 rows each)
    int warp_n = wid >> 1;       // 4 warps along N (32 cols each)
    int row0 = blockIdx.y * GBM;
    int col0 = blockIdx.x * GBN;
    int gid = lane >> 2;         // 0..7
    int tig = lane & 3;          // 0..3

    uint32_t saBase = smem_u32(&sA[0][0]);
    uint32_t sbBase = smem_u32(&sB[0][0]);

    float acc[4][4][4];
#pragma unroll
    for (int i = 0; i < 4; i++)
#pragma unroll
        for (int j = 0; j < 4; j++)
#pragma unroll
            for (int c = 0; c < 4; c++) acc[i][j][c] = 0.f;

    // async copy of one k-tile into stage buf: 128 rows x 16 floats per array;
    // 512 float4 slots per array, 256 threads -> 2 each
    auto issue = [&](int kt, int buf) {
#pragma unroll
        for (int i = 0; i < 2; i++) {
            int lin = i * 256 + tid;
            int row = lin >> 2;
            int f = lin & 3;
            uint32_t off = (uint32_t)(buf * GBM * SPAD + row * SPAD + f * 4) * 4u;
            int gr = row0 + row;
            int sz = (gr < M) ? 16 : 0;
            CP_ASYNC16Z(saBase + off, A + (size_t)gr * K + kt + f * 4, sz);
            CP_ASYNC16(sbBase + off, Bw + (size_t)(col0 + row) * K + kt + f * 4);
        }
        CP_COMMIT();
    };

    const int T = K / GBK;
    issue(0, 0);
    for (int t = 0; t < T; t++) {
        if (t + 1 < T) {
            issue((t + 1) * GBK, (t + 1) & 1);
            CP_WAIT(1);
        } else {
            CP_WAIT(0);
        }
        __syncthreads();
        int buf = t & 1;
#pragma unroll
        for (int kk = 0; kk < GBK; kk += 8) {
            uint32_t af[4][4], bf[4][2];
#pragma unroll
            for (int mt = 0; mt < 4; mt++) {
                int r = warp_m * 64 + mt * 16 + gid;
                af[mt][0] = f2tf32(sA[buf][r * SPAD + kk + tig]);
                af[mt][1] = f2tf32(sA[buf][(r + 8) * SPAD + kk + tig]);
                af[mt][2] = f2tf32(sA[buf][r * SPAD + kk + tig + 4]);
                af[mt][3] = f2tf32(sA[buf][(r + 8) * SPAD + kk + tig + 4]);
            }
#pragma unroll
            for (int nt = 0; nt < 4; nt++) {
                int n = warp_n * 32 + nt * 8 + gid;
                bf[nt][0] = f2tf32(sB[buf][n * SPAD + kk + tig]);
                bf[nt][1] = f2tf32(sB[buf][n * SPAD + kk + tig + 4]);
            }
#pragma unroll
            for (int mt = 0; mt < 4; mt++)
#pragma unroll
                for (int nt = 0; nt < 4; nt++) {
                    asm volatile(
                        "mma.sync.aligned.m16n8k8.row.col.f32.tf32.tf32.f32 "
                        "{%0,%1,%2,%3}, {%4,%5,%6,%7}, {%8,%9}, {%0,%1,%2,%3};"
                        : "+f"(acc[mt][nt][0]), "+f"(acc[mt][nt][1]),
                          "+f"(acc[mt][nt][2]), "+f"(acc[mt][nt][3])
                        : "r"(af[mt][0]), "r"(af[mt][1]), "r"(af[mt][2]), "r"(af[mt][3]),
                          "r"(bf[nt][0]), "r"(bf[nt][1]));
                }
        }
        __syncthreads();
    }

    // epilogue: bias (+relu), store; fused BN column partials for which==1
    if (which == 1) {
        if (tid < GBN) { s_bns[tid] = 0.f; s_bnq[tid] = 0.f; }
        __syncthreads();
    }
    float cs[4][2], cq[4][2];
#pragma unroll
    for (int nt = 0; nt < 4; nt++) {
        cs[nt][0] = cs[nt][1] = cq[nt][0] = cq[nt][1] = 0.f;
        int cb = col0 + warp_n * 32 + nt * 8 + 2 * tig;
        float bv0 = __ldg(&bias[cb]);
        float bv1 = __ldg(&bias[cb + 1]);
#pragma unroll
        for (int mt = 0; mt < 4; mt++) {
            int r = row0 + warp_m * 64 + mt * 16 + gid;
            float v0 = acc[mt][nt][0] + bv0;
            float v1 = acc[mt][nt][1] + bv1;
            float v2 = acc[mt][nt][2] + bv0;
            float v3 = acc[mt][nt][3] + bv1;
            if (do_relu) {
                v0 = fmaxf(v0, 0.f); v1 = fmaxf(v1, 0.f);
                v2 = fmaxf(v2, 0.f); v3 = fmaxf(v3, 0.f);
            }
            if (r < M) {
                *(float2*)&C[(size_t)r * N + cb] = make_float2(v0, v1);
                cs[nt][0] += v0; cq[nt][0] += v0 * v0;
                cs[nt][1] += v1; cq[nt][1] += v1 * v1;
            }
            if (r + 8 < M) {
                *(float2*)&C[(size_t)(r + 8) * N + cb] = make_float2(v2, v3);
                cs[nt][0] += v2; cq[nt][0] += v2 * v2;
                cs[nt][1] += v3; cq[nt][1] += v3 * v3;
            }
        }
    }
    if (which == 1) {
#pragma unroll
        for (int nt = 0; nt < 4; nt++) {
            int cl = warp_n * 32 + nt * 8 + 2 * tig;
            atomicAdd(&s_bns[cl], cs[nt][0]);
            atomicAdd(&s_bns[cl + 1], cs[nt][1]);
            atomicAdd(&s_bnq[cl], cq[nt][0]);
            atomicAdd(&s_bnq[cl + 1], cq[nt][1]);
        }
        __syncthreads();
        if (tid < GBN) {
            atomicAdd(&g_bnsum[col0 + tid], s_bns[tid]);
            atomicAdd(&g_bnsumsq[col0 + tid], s_bnq[tid]);
        }
    }
}

// ---------------- BN finalize + normalize --------------------------------------
__global__ void k_bnfinal(const float* __restrict__ gamma,
                          const float* __restrict__ beta) {
    int d = threadIdx.x;  // 256
    float mean = g_bnsum[d] * (1.0f / (float)NNODES);
    float var = g_bnsumsq[d] * (1.0f / (float)NNODES) - mean * mean;
    float inv = rsqrtf(var + BN_EPS);
    float sc = inv * gamma[d];
    g_scale[d] = sc;
    g_shift[d] = beta[d] - mean * sc;
}
__global__ void k_norm(float* __restrict__ out) {
    int i = blockIdx.x * blockDim.x + threadIdx.x;   // over N*DIM/4
    if (i >= NNODES * DIM / 4) return;
    int base = i * 4;
    int d = base & (DIM - 1);
    float4 v = *(const float4*)&g_bufA[base];
    float4 o;
    o.x = v.x * g_scale[d + 0] + g_shift[d + 0];
    o.y = v.y * g_scale[d + 1] + g_shift[d + 1];
    o.z = v.z * g_scale[d + 2] + g_shift[d + 2];
    o.w = v.w * g_scale[d + 3] + g_shift[d + 3];
    *(float4*)&out[base] = o;
}

// ---------------- launch -------------------------------------------------------
extern "C" void kernel_launch(void* const* d_in, const int* in_sizes, int n_in,
                              void* d_out, int out_size) {
    const float* node_feats = (const float*)d_in[0];
    const void* src         = d_in[1];
    const void* dst         = d_in[2];
    const float* eps        = (const float*)d_in[3];
    const float* W1         = (const float*)d_in[4];
    const float* b1         = (const float*)d_in[5];
    const float* W2         = (const float*)d_in[6];
    const float* b2         = (const float*)d_in[7];
    const float* gamma      = (const float*)d_in[8];
    const float* beta       = (const float*)d_in[9];
    float* out = (float*)d_out;

    // CSR build
    k_zero<<<(NNODES + 255) / 256, 256>>>((const int*)dst);
    k_hist<<<(NEDGES + 255) / 256, 256>>>(dst);
    k_scan1<<<SCAN_NB, SCAN_CHUNK>>>();
    k_scan2<<<1, 128>>>();
    k_scan3<<<(NNODES + 255) / 256, 256>>>();
    k_scatter<<<(NEDGES + 255) / 256, 256>>>(src, dst);

    // weight transposes (independent of the above)
    {
        dim3 b(32, 8);
        k_transpose<<<dim3(DIM2 / 32, DIM / 32), b>>>(W1, DIM, DIM2, 0);
        k_transpose<<<dim3(DIM / 32, DIM2 / 32), b>>>(W2, DIM2, DIM, 1);
    }

    // aggregation -> h0 (g_bufA)
    k_aggregate<<<NNODES, DIM>>>(node_feats, eps);

    const int MROWS = (NNODES + GBM - 1) / GBM;   // 782
    // GEMM1: h1 = relu(h0 @ W1 + b1) -> g_bufB
    k_gemm_tc<<<dim3(DIM2 / GBN, MROWS), 256>>>(0, b1, NNODES, DIM2, DIM);
    // GEMM2: h2 = h1 @ W2 + b2 -> g_bufA (+ BN stats)
    k_gemm_tc<<<dim3(DIM / GBN, MROWS), 256>>>(1, b2, NNODES, DIM, DIM2);

    // BN finalize + normalize
    k_bnfinal<<<1, DIM>>>(gamma, beta);
    k_norm<<<(NNODES * DIM / 4 + 255) / 256, 256>>>(out);
}

// round 8
// speedup vs baseline: 2.6772x; 1.1693x over previous
#include <cuda_runtime.h>
#include <cuda_bf16.h>
#include <cstdint>

#define NNODES 100000
#define NEDGES 1600000
#define DIM 256
#define DIM2 512
#define BN_EPS 1e-5f

// ---------------- scratch (static device globals; no dynamic alloc) -----------
__device__ int    g_is64;
__device__ int    g_deg[NNODES];
__device__ int    g_rowptr[NNODES + 1];
__device__ int    g_cursor[NNODES];
__device__ int    g_edgesrc[NEDGES];
__device__ float  g_bufA[(size_t)NNODES * DIM];    // h0, later h2
__device__ float  g_bufB[(size_t)NNODES * DIM2];   // h1
__device__ float  g_WT1[(size_t)DIM2 * DIM];       // W1^T  [512][256]
__device__ float  g_WT2[(size_t)DIM * DIM2];       // W2^T  [256][512]
__device__ float  g_bnsum[DIM];
__device__ float  g_bnsumsq[DIM];
__device__ float  g_scale[DIM];
__device__ float  g_shift[DIM];

#define SCAN_CHUNK 1024
#define SCAN_NB ((NNODES + SCAN_CHUNK - 1) / SCAN_CHUNK)   // 98
__device__ int g_bsum[SCAN_NB];
__device__ int g_boff[SCAN_NB];

// ---------------- helpers ------------------------------------------------------
__device__ __forceinline__ uint32_t smem_u32(const void* p) {
    uint32_t a;
    asm("{ .reg .u64 t; cvta.to.shared.u64 t, %1; cvt.u32.u64 %0, t; }"
        : "=r"(a) : "l"(p));
    return a;
}
__device__ __forceinline__ uint32_t f2tf32(float f) {
    uint32_t r;
    asm("cvt.rna.tf32.f32 %0, %1;" : "=r"(r) : "f"(f));
    return r;
}
#define CP_ASYNC16Z(dst, src, sz) \
    asm volatile("cp.async.cg.shared.global [%0], [%1], 16, %2;" \
                 :: "r"(dst), "l"(src), "r"(sz) : "memory")
#define CP_ASYNC16(dst, src) \
    asm volatile("cp.async.cg.shared.global [%0], [%1], 16;" \
                 :: "r"(dst), "l"(src) : "memory")
#define CP_COMMIT() asm volatile("cp.async.commit_group;" ::: "memory")
#define CP_WAIT(n)  asm volatile("cp.async.wait_group %0;" :: "n"(n) : "memory")

__device__ __forceinline__ int load_idx(const void* p, int e, int is64) {
    return is64 ? (int)((const long long*)p)[e] : ((const int*)p)[e];
}

// ---------------- zero + index-dtype detect ------------------------------------
__global__ void k_zero(const int* __restrict__ dst_raw) {
    int i = blockIdx.x * blockDim.x + threadIdx.x;
    if (i < NNODES) g_deg[i] = 0;
    if (i < DIM) { g_bnsum[i] = 0.f; g_bnsumsq[i] = 0.f; }
    if (i == 0) {
        int is64 = 1;
        for (int k = 0; k < 64; k++)
            if (dst_raw[2 * k + 1] != 0) { is64 = 0; break; }
        g_is64 = is64;
    }
}

// ---------------- CSR build ----------------------------------------------------
// 2 edges per thread, vectorized index loads
__global__ void k_hist(const void* __restrict__ dst) {
    int e0 = (blockIdx.x * blockDim.x + threadIdx.x) * 2;
    int is64 = g_is64;
    if (e0 + 1 < NEDGES) {
        int d0, d1;
        if (is64) {
            longlong2 v = __ldg(&((const longlong2*)dst)[e0 >> 1]);
            d0 = (int)v.x; d1 = (int)v.y;
        } else {
            int2 v = __ldg(&((const int2*)dst)[e0 >> 1]);
            d0 = v.x; d1 = v.y;
        }
        atomicAdd(&g_deg[d0], 1);
        atomicAdd(&g_deg[d1], 1);
    } else if (e0 < NEDGES) {
        atomicAdd(&g_deg[load_idx(dst, e0, is64)], 1);
    }
}
__global__ void k_scan1() {
    __shared__ int sm[SCAN_CHUNK];
    int b = blockIdx.x, tid = threadIdx.x;
    int idx = b * SCAN_CHUNK + tid;
    int v = (idx < NNODES) ? g_deg[idx] : 0;
    sm[tid] = v;
    __syncthreads();
    for (int s = 1; s < SCAN_CHUNK; s <<= 1) {
        int t = (tid >= s) ? sm[tid - s] : 0;
        __syncthreads();
        sm[tid] += t;
        __syncthreads();
    }
    if (idx < NNODES) g_rowptr[idx] = sm[tid] - v;
    if (tid == SCAN_CHUNK - 1) g_bsum[b] = sm[tid];
}
__global__ void k_scan2() {
    __shared__ int sm[128];
    int tid = threadIdx.x;
    int v = (tid < SCAN_NB) ? g_bsum[tid] : 0;
    sm[tid] = v;
    __syncthreads();
    for (int s = 1; s < 128; s <<= 1) {
        int t = (tid >= s) ? sm[tid - s] : 0;
        __syncthreads();
        sm[tid] += t;
        __syncthreads();
    }
    if (tid < SCAN_NB) g_boff[tid] = sm[tid] - v;
    if (tid == 127) g_rowptr[NNODES] = sm[127];
}
__global__ void k_scan3() {
    int i = blockIdx.x * blockDim.x + threadIdx.x;
    if (i < NNODES) {
        int r = g_rowptr[i] + g_boff[i >> 10];
        g_rowptr[i] = r;
        g_cursor[i] = r;
    }
}
__global__ void k_scatter(const void* __restrict__ src,
                          const void* __restrict__ dst) {
    int e = blockIdx.x * blockDim.x + threadIdx.x;
    int is64 = g_is64;
    if (e < NEDGES) {
        int d = load_idx(dst, e, is64);
        int pos = atomicAdd(&g_cursor[d], 1);
        g_edgesrc[pos] = load_idx(src, e, is64);
    }
}

// ---------------- aggregation: h0 = (1+eps)*x + sum_{in-edges} x[src] ----------
// 4 nodes per block; 64-thread group per node; float4 per thread; 4-way unroll
__global__ __launch_bounds__(256) void k_aggregate(
    const float* __restrict__ x, const float* __restrict__ eps) {
    int grp = threadIdx.x >> 6;              // 0..3
    int t = threadIdx.x & 63;                // float4 column
    int n = blockIdx.x * 4 + grp;
    if (n >= NNODES) return;
    const float4* x4 = (const float4*)x;

    int beg = g_rowptr[n];
    int end = g_rowptr[n + 1];
    float4 a0 = make_float4(0.f, 0.f, 0.f, 0.f);
    float4 a1 = make_float4(0.f, 0.f, 0.f, 0.f);
    float4 a2 = make_float4(0.f, 0.f, 0.f, 0.f);
    float4 a3 = make_float4(0.f, 0.f, 0.f, 0.f);
    int j = beg;
    for (; j + 4 <= end; j += 4) {
        int s0 = g_edgesrc[j];
        int s1 = g_edgesrc[j + 1];
        int s2 = g_edgesrc[j + 2];
        int s3 = g_edgesrc[j + 3];
        float4 v0 = __ldg(&x4[(size_t)s0 * 64 + t]);
        float4 v1 = __ldg(&x4[(size_t)s1 * 64 + t]);
        float4 v2 = __ldg(&x4[(size_t)s2 * 64 + t]);
        float4 v3 = __ldg(&x4[(size_t)s3 * 64 + t]);
        a0.x += v0.x; a0.y += v0.y; a0.z += v0.z; a0.w += v0.w;
        a1.x += v1.x; a1.y += v1.y; a1.z += v1.z; a1.w += v1.w;
        a2.x += v2.x; a2.y += v2.y; a2.z += v2.z; a2.w += v2.w;
        a3.x += v3.x; a3.y += v3.y; a3.z += v3.z; a3.w += v3.w;
    }
    for (; j < end; j++) {
        int s = g_edgesrc[j];
        float4 v = __ldg(&x4[(size_t)s * 64 + t]);
        a0.x += v.x; a0.y += v.y; a0.z += v.z; a0.w += v.w;
    }
    float e0 = __ldg(&eps[0]);
    float4 self = __ldg(&x4[(size_t)n * 64 + t]);
    float4 o;
    o.x = (1.f + e0) * self.x + ((a0.x + a1.x) + (a2.x + a3.x));
    o.y = (1.f + e0) * self.y + ((a0.y + a1.y) + (a2.y + a3.y));
    o.z = (1.f + e0) * self.z + ((a0.z + a1.z) + (a2.z + a3.z));
    o.w = (1.f + e0) * self.w + ((a0.w + a1.w) + (a2.w + a3.w));
    ((float4*)g_bufA)[(size_t)n * 64 + t] = o;
}

// ---------------- weight transpose: WT[n][k] = W[k][n] -------------------------
__global__ void k_transpose(const float* __restrict__ W, int rows, int cols, int which) {
    __shared__ float t[32][33];
    float* out = which ? g_WT2 : g_WT1;
    int bx = blockIdx.x * 32, by = blockIdx.y * 32;
    for (int i = threadIdx.y; i < 32; i += 8)
        t[i][threadIdx.x] = W[(size_t)(by + i) * cols + bx + threadIdx.x];
    __syncthreads();
    for (int i = threadIdx.y; i < 32; i += 8)
        out[(size_t)(bx + i) * rows + by + threadIdx.x] = t[threadIdx.x][i];
}

// ---------------- tf32 mma.sync GEMM, cp.async 2-stage pipeline ----------------
// which==0: A=g_bufA [M,256], B=g_WT1 -> C=g_bufB [M,512], ReLU
// which==1: A=g_bufB [M,512], B=g_WT2 -> C=g_bufA [M,256], fused BN stats
#define GBM 128
#define GBN 128
#define GBK 16
#define SPAD 20     // floats per smem row (16 data + 4 pad); 80B, 16B-aligned

__global__ __launch_bounds__(256, 2)
void k_gemm_tc(int which, const float* __restrict__ bias, int M, int N, int K) {
    const float* A  = which ? g_bufB : g_bufA;
    const float* Bw = which ? g_WT2 : g_WT1;
    float* C        = which ? g_bufA : g_bufB;
    const int do_relu = (which == 0);

    __shared__ float sA[2][GBM * SPAD];   // 2 stages x 10KB
    __shared__ float sB[2][GBM * SPAD];
    __shared__ float s_bns[GBN], s_bnq[GBN];

    int tid = threadIdx.x;
    int wid = tid >> 5;
    int lane = tid & 31;
    int warp_m = wid & 1;        // 2 warps along M (64 rows each)
    int warp_n = wid >> 1;       // 4 warps along N (32 cols each)
    int row0 = blockIdx.y * GBM;
    int col0 = blockIdx.x * GBN;
    int gid = lane >> 2;         // 0..7
    int tig = lane & 3;          // 0..3

    uint32_t saBase = smem_u32(&sA[0][0]);
    uint32_t sbBase = smem_u32(&sB[0][0]);

    float acc[4][4][4];
#pragma unroll
    for (int i = 0; i < 4; i++)
#pragma unroll
        for (int j = 0; j < 4; j++)
#pragma unroll
            for (int c = 0; c < 4; c++) acc[i][j][c] = 0.f;

    auto issue = [&](int kt, int buf) {
#pragma unroll
        for (int i = 0; i < 2; i++) {
            int lin = i * 256 + tid;
            int row = lin >> 2;
            int f = lin & 3;
            uint32_t off = (uint32_t)(buf * GBM * SPAD + row * SPAD + f * 4) * 4u;
            int gr = row0 + row;
            int sz = (gr < M) ? 16 : 0;
            CP_ASYNC16Z(saBase + off, A + (size_t)gr * K + kt + f * 4, sz);
            CP_ASYNC16(sbBase + off, Bw + (size_t)(col0 + row) * K + kt + f * 4);
        }
        CP_COMMIT();
    };

    const int T = K / GBK;
    issue(0, 0);
    for (int t = 0; t < T; t++) {
        if (t + 1 < T) {
            issue((t + 1) * GBK, (t + 1) & 1);
            CP_WAIT(1);
        } else {
            CP_WAIT(0);
        }
        __syncthreads();
        int buf = t & 1;
#pragma unroll
        for (int kk = 0; kk < GBK; kk += 8) {
            uint32_t af[4][4], bf[4][2];
#pragma unroll
            for (int mt = 0; mt < 4; mt++) {
                int r = warp_m * 64 + mt * 16 + gid;
                af[mt][0] = f2tf32(sA[buf][r * SPAD + kk + tig]);
                af[mt][1] = f2tf32(sA[buf][(r + 8) * SPAD + kk + tig]);
                af[mt][2] = f2tf32(sA[buf][r * SPAD + kk + tig + 4]);
                af[mt][3] = f2tf32(sA[buf][(r + 8) * SPAD + kk + tig + 4]);
            }
#pragma unroll
            for (int nt = 0; nt < 4; nt++) {
                int n = warp_n * 32 + nt * 8 + gid;
                bf[nt][0] = f2tf32(sB[buf][n * SPAD + kk + tig]);
                bf[nt][1] = f2tf32(sB[buf][n * SPAD + kk + tig + 4]);
            }
#pragma unroll
            for (int mt = 0; mt < 4; mt++)
#pragma unroll
                for (int nt = 0; nt < 4; nt++) {
                    asm volatile(
                        "mma.sync.aligned.m16n8k8.row.col.f32.tf32.tf32.f32 "
                        "{%0,%1,%2,%3}, {%4,%5,%6,%7}, {%8,%9}, {%0,%1,%2,%3};"
                        : "+f"(acc[mt][nt][0]), "+f"(acc[mt][nt][1]),
                          "+f"(acc[mt][nt][2]), "+f"(acc[mt][nt][3])
                        : "r"(af[mt][0]), "r"(af[mt][1]), "r"(af[mt][2]), "r"(af[mt][3]),
                          "r"(bf[nt][0]), "r"(bf[nt][1]));
                }
        }
        __syncthreads();
    }

    // epilogue: bias (+relu), store; fused BN column partials for which==1
    if (which == 1) {
        if (tid < GBN) { s_bns[tid] = 0.f; s_bnq[tid] = 0.f; }
        __syncthreads();
    }
    float cs[4][2], cq[4][2];
#pragma unroll
    for (int nt = 0; nt < 4; nt++) {
        cs[nt][0] = cs[nt][1] = cq[nt][0] = cq[nt][1] = 0.f;
        int cb = col0 + warp_n * 32 + nt * 8 + 2 * tig;
        float bv0 = __ldg(&bias[cb]);
        float bv1 = __ldg(&bias[cb + 1]);
#pragma unroll
        for (int mt = 0; mt < 4; mt++) {
            int r = row0 + warp_m * 64 + mt * 16 + gid;
            float v0 = acc[mt][nt][0] + bv0;
            float v1 = acc[mt][nt][1] + bv1;
            float v2 = acc[mt][nt][2] + bv0;
            float v3 = acc[mt][nt][3] + bv1;
            if (do_relu) {
                v0 = fmaxf(v0, 0.f); v1 = fmaxf(v1, 0.f);
                v2 = fmaxf(v2, 0.f); v3 = fmaxf(v3, 0.f);
            }
            if (r < M) {
                *(float2*)&C[(size_t)r * N + cb] = make_float2(v0, v1);
                cs[nt][0] += v0; cq[nt][0] += v0 * v0;
                cs[nt][1] += v1; cq[nt][1] += v1 * v1;
            }
            if (r + 8 < M) {
                *(float2*)&C[(size_t)(r + 8) * N + cb] = make_float2(v2, v3);
                cs[nt][0] += v2; cq[nt][0] += v2 * v2;
                cs[nt][1] += v3; cq[nt][1] += v3 * v3;
            }
        }
    }
    if (which == 1) {
#pragma unroll
        for (int nt = 0; nt < 4; nt++) {
            int cl = warp_n * 32 + nt * 8 + 2 * tig;
            atomicAdd(&s_bns[cl], cs[nt][0]);
            atomicAdd(&s_bns[cl + 1], cs[nt][1]);
            atomicAdd(&s_bnq[cl], cq[nt][0]);
            atomicAdd(&s_bnq[cl + 1], cq[nt][1]);
        }
        __syncthreads();
        if (tid < GBN) {
            atomicAdd(&g_bnsum[col0 + tid], s_bns[tid]);
            atomicAdd(&g_bnsumsq[col0 + tid], s_bnq[tid]);
        }
    }
}

// ---------------- BN finalize + normalize --------------------------------------
__global__ void k_bnfinal(const float* __restrict__ gamma,
                          const float* __restrict__ beta) {
    int d = threadIdx.x;  // 256
    float mean = g_bnsum[d] * (1.0f / (float)NNODES);
    float var = g_bnsumsq[d] * (1.0f / (float)NNODES) - mean * mean;
    float inv = rsqrtf(var + BN_EPS);
    float sc = inv * gamma[d];
    g_scale[d] = sc;
    g_shift[d] = beta[d] - mean * sc;
}
__global__ void k_norm(float* __restrict__ out) {
    int i = blockIdx.x * blockDim.x + threadIdx.x;   // over N*DIM/4
    if (i >= NNODES * DIM / 4) return;
    int base = i * 4;
    int d = base & (DIM - 1);
    float4 v = *(const float4*)&g_bufA[base];
    float4 o;
    o.x = v.x * g_scale[d + 0] + g_shift[d + 0];
    o.y = v.y * g_scale[d + 1] + g_shift[d + 1];
    o.z = v.z * g_scale[d + 2] + g_shift[d + 2];
    o.w = v.w * g_scale[d + 3] + g_shift[d + 3];
    *(float4*)&out[base] = o;
}

// ---------------- launch -------------------------------------------------------
extern "C" void kernel_launch(void* const* d_in, const int* in_sizes, int n_in,
                              void* d_out, int out_size) {
    const float* node_feats = (const float*)d_in[0];
    const void* src         = d_in[1];
    const void* dst         = d_in[2];
    const float* eps        = (const float*)d_in[3];
    const float* W1         = (const float*)d_in[4];
    const float* b1         = (const float*)d_in[5];
    const float* W2         = (const float*)d_in[6];
    const float* b2         = (const float*)d_in[7];
    const float* gamma      = (const float*)d_in[8];
    const float* beta       = (const float*)d_in[9];
    float* out = (float*)d_out;

    // CSR build
    k_zero<<<(NNODES + 255) / 256, 256>>>((const int*)dst);
    k_hist<<<(NEDGES / 2 + 255) / 256, 256>>>(dst);
    k_scan1<<<SCAN_NB, SCAN_CHUNK>>>();
    k_scan2<<<1, 128>>>();
    k_scan3<<<(NNODES + 255) / 256, 256>>>();
    k_scatter<<<(NEDGES + 255) / 256, 256>>>(src, dst);

    // weight transposes (independent of the above)
    {
        dim3 b(32, 8);
        k_transpose<<<dim3(DIM2 / 32, DIM / 32), b>>>(W1, DIM, DIM2, 0);
        k_transpose<<<dim3(DIM / 32, DIM2 / 32), b>>>(W2, DIM2, DIM, 1);
    }

    // aggregation -> h0 (g_bufA); 4 nodes per block
    k_aggregate<<<(NNODES + 3) / 4, 256>>>(node_feats, eps);

    const int MROWS = (NNODES + GBM - 1) / GBM;   // 782
    // GEMM1: h1 = relu(h0 @ W1 + b1) -> g_bufB
    k_gemm_tc<<<dim3(DIM2 / GBN, MROWS), 256>>>(0, b1, NNODES, DIM2, DIM);
    // GEMM2: h2 = h1 @ W2 + b2 -> g_bufA (+ BN stats)
    k_gemm_tc<<<dim3(DIM / GBN, MROWS), 256>>>(1, b2, NNODES, DIM, DIM2);

    // BN finalize + normalize
    k_bnfinal<<<1, DIM>>>(gamma, beta);
    k_norm<<<(NNODES * DIM / 4 + 255) / 256, 256>>>(out);
}